// round 11
// baseline (speedup 1.0000x reference)
#include <cuda_runtime.h>
#include <cstdint>

// Problem shape (fixed)
#define Bn   16
#define Tn   8192
#define Cn   128
#define NCH  128           // chunks along T
#define CT   64            // timesteps per chunk
#define HT   32            // timesteps per half-chunk
#define HC   64            // float2 lanes per half (2 channels/thread)
#define GS   16            // chunks per lookback group
#define NG   (NCH / GS)    // 8 groups per batch

// ---------------- device scratch (static; no allocations) ----------------
__device__ float4 g_locxn[Bn * NCH * HC];  // per-chunk local {Sx.a,Sx.b,Sn.a,Sn.b}
__device__ float2 g_locq [Bn * NCH * HC];  // per-chunk local Ssq
__device__ float4 g_grpxn[Bn * NG * HC];   // per-group totals (x,n)
__device__ float2 g_grpq [Bn * NG * HC];   // per-group totals (q)
__device__ unsigned g_flagL[2 * Bn * NCH]; // per-chunk flags: [phase1 | phase2]
__device__ unsigned g_flagG[2 * Bn * NG];  // per-group flags: [phase1 | phase2]

// ---------------- helpers ----------------
__device__ __forceinline__ unsigned ld_acquire(const unsigned* p) {
    unsigned v;
    asm volatile("ld.acquire.gpu.u32 %0, [%1];" : "=r"(v) : "l"(p) : "memory");
    return v;
}
__device__ __forceinline__ void st_release(unsigned* p, unsigned v) {
    asm volatile("st.release.gpu.u32 [%0], %1;" :: "l"(p), "r"(v) : "memory");
}
__device__ __forceinline__ float frcp(float x) {
    float r; asm("rcp.approx.ftz.f32 %0, %1;" : "=f"(r) : "f"(x)); return r;
}
__device__ __forceinline__ float frsq(float x) {
    float r; asm("rsqrt.approx.ftz.f32 %0, %1;" : "=f"(r) : "f"(x)); return r;
}
__device__ __forceinline__ void add4(float4& a, const float4& b) {
    a.x += b.x; a.y += b.y; a.z += b.z; a.w += b.w;
}

__global__ void revin_init_flags() {
    int i = blockIdx.x * blockDim.x + threadIdx.x;
    if (i < 2 * Bn * NCH) g_flagL[i] = 0u;
    if (i < 2 * Bn * NG)  g_flagG[i] = 0u;
}

// ---------------- main kernel ----------------
// grid = (NCH, Bn), block = 128 threads.
// h = tid>>6 selects time-half; l = tid&63 owns channels (2l, 2l+1).
__global__ __launch_bounds__(128) void revin_kernel(
    const float* __restrict__ x,
    const float* __restrict__ mask,
    float* __restrict__ out)
{
    __shared__ float4 s_pw[2][HC];                       // within-group partials
    __shared__ float4 s_pg[2][HC];                       // group-total partials
    __shared__ float2 s_h0x[HC], s_h0n[HC], s_h0q[HC];   // half0 locals

    const int tid = threadIdx.x;
    const int h = tid >> 6;
    const int l = tid & 63;
    const int k = blockIdx.x;            // chunk along T
    const int b = blockIdx.y;            // batch
    const int bN = b * NCH;
    const int bG = b * NG;
    const int g = k >> 4;                // group index
    const int p = k & (GS - 1);          // position within group
    const int gbase = k & ~(GS - 1);     // first chunk of group

    const size_t base = (size_t)((b * Tn + k * CT + h * HT) * Cn) + 2 * l;
    const float2* __restrict__ px = (const float2*)(x    + base);
    const float2* __restrict__ pm = (const float2*)(mask + base);
    float2*       __restrict__ po = (float2*)(out + base);
    // per-timestep stride in float2 units = Cn/2 = 64

    unsigned* flagL1 = g_flagL + bN;
    unsigned* flagL2 = g_flagL + Bn * NCH + bN;
    unsigned* flagG1 = g_flagG + bG;
    unsigned* flagG2 = g_flagG + Bn * NG + bG;
    const int ai = (bN + k) * HC + l;
    const int gi = (bG + g) * HC + l;

    // ---------------- Phase 1: local sums of x and nm ----------------
    float2 Lx = make_float2(0.f, 0.f);
    unsigned mA = 0u, mB = 0u;       // bit t set => observed at local timestep t
    #pragma unroll 8
    for (int t = 0; t < HT; ++t) {
        float2 xv = px[t * 64];
        float2 mv = pm[t * 64];
        Lx.x += xv.x; Lx.y += xv.y;
        mA |= (unsigned)(mv.x == 0.f) << t;
        mB |= (unsigned)(mv.y == 0.f) << t;
    }
    float2 Ln = make_float2((float)__popc(mA), (float)__popc(mB));

    if (h == 0) { s_h0x[l] = Lx; s_h0n[l] = Ln; }
    __syncthreads();
    float2 cx = make_float2(0.f, 0.f), cn = make_float2(0.f, 0.f);  // chunk totals (h==1)
    if (h == 1) {
        float2 h0x = s_h0x[l], h0n = s_h0n[l];
        cx = make_float2(h0x.x + Lx.x, h0x.y + Lx.y);
        cn = make_float2(h0n.x + Ln.x, h0n.y + Ln.y);
        g_locxn[ai] = make_float4(cx.x, cx.y, cn.x, cn.y);
    }
    __syncthreads();
    if (tid == 0) { __threadfence(); st_release(&flagL1[k], 1u); }

    // ---------------- Lookback 1: two-level, parallel wait ----------------
    if (tid < p) {
        while (ld_acquire(&flagL1[gbase + tid]) == 0u) __nanosleep(40);
    } else if (tid >= 64 && tid < 64 + g) {
        while (ld_acquire(&flagG1[tid - 64]) == 0u) __nanosleep(40);
    }
    __syncthreads();
    {
        float4 sw = make_float4(0.f, 0.f, 0.f, 0.f);
        float4 sg = make_float4(0.f, 0.f, 0.f, 0.f);
        #pragma unroll 4
        for (int j = gbase + h; j < k; j += 2)   // within-group locals
            add4(sw, g_locxn[(bN + j) * HC + l]);
        #pragma unroll 4
        for (int j = h; j < g; j += 2)           // preceding group totals
            add4(sg, g_grpxn[(bG + j) * HC + l]);
        s_pw[h][l] = sw;
        s_pg[h][l] = sg;
    }
    __syncthreads();

    float4 exw = s_pw[0][l]; add4(exw, s_pw[1][l]);   // within-group exclusive
    float4 exg = s_pg[0][l]; add4(exg, s_pg[1][l]);   // groups exclusive
    float2 exx = make_float2(exw.x + exg.x, exw.y + exg.y);
    float2 exn = make_float2(exw.z + exg.z, exw.w + exg.w);

    if (p == GS - 1) {   // last chunk of group publishes the group total
        if (h == 1) {
            g_grpxn[gi] = make_float4(exw.x + cx.x, exw.y + cx.y,
                                      exw.z + cn.x, exw.w + cn.y);
        }
        __syncthreads();
        if (tid == 0) { __threadfence(); st_release(&flagG1[g], 1u); }
    }

    // this thread's starting state (half1 adds half0's local)
    float2 ssx = exx, ssn = exn;
    if (h == 1) {
        float2 h0x = s_h0x[l], h0n = s_h0n[l];
        ssx.x += h0x.x; ssx.y += h0x.y;
        ssn.x += h0n.x; ssn.y += h0n.y;
    }

    // ---------------- Phase 2: running mean; half-local Ssq ----------------
    float2 sx = ssx, sn = ssn;
    float2 lsq = make_float2(0.f, 0.f);
    #pragma unroll 8
    for (int t = 0; t < HT; ++t) {
        float2 xv = px[t * 64];
        float nm, nn, mean, d;

        nm = (float)((mA >> t) & 1u);
        sx.x += xv.x; sn.x += nm;
        nn = fmaxf(sn.x, 1.f);
        mean = sx.x * frcp(nn);
        d = (xv.x - mean) * nm;
        lsq.x = fmaf(d, d, lsq.x);

        nm = (float)((mB >> t) & 1u);
        sx.y += xv.y; sn.y += nm;
        nn = fmaxf(sn.y, 1.f);
        mean = sx.y * frcp(nn);
        d = (xv.y - mean) * nm;
        lsq.y = fmaf(d, d, lsq.y);
    }

    if (h == 0) { s_h0q[l] = lsq; }
    __syncthreads();
    float2 cq = make_float2(0.f, 0.f);
    if (h == 1) {
        float2 h0q = s_h0q[l];
        cq = make_float2(h0q.x + lsq.x, h0q.y + lsq.y);
        g_locq[ai] = cq;
    }
    __syncthreads();
    if (tid == 0) { __threadfence(); st_release(&flagL2[k], 1u); }

    // ---------------- Lookback 2: two-level ----------------
    if (tid < p) {
        while (ld_acquire(&flagL2[gbase + tid]) == 0u) __nanosleep(40);
    } else if (tid >= 64 && tid < 64 + g) {
        while (ld_acquire(&flagG2[tid - 64]) == 0u) __nanosleep(40);
    }
    __syncthreads();
    {
        float2 qw = make_float2(0.f, 0.f);
        float2 qg = make_float2(0.f, 0.f);
        #pragma unroll 4
        for (int j = gbase + h; j < k; j += 2) {
            float2 q = g_locq[(bN + j) * HC + l];
            qw.x += q.x; qw.y += q.y;
        }
        #pragma unroll 4
        for (int j = h; j < g; j += 2) {
            float2 q = g_grpq[(bG + j) * HC + l];
            qg.x += q.x; qg.y += q.y;
        }
        s_pw[h][l] = make_float4(qw.x, qw.y, qg.x, qg.y);
    }
    __syncthreads();

    float4 q0 = s_pw[0][l], q1 = s_pw[1][l];
    float2 exqw = make_float2(q0.x + q1.x, q0.y + q1.y);   // within-group
    float2 exq  = make_float2(exqw.x + q0.z + q1.z, exqw.y + q0.w + q1.w);

    if (p == GS - 1) {
        if (h == 1) {
            g_grpq[gi] = make_float2(exqw.x + cq.x, exqw.y + cq.y);
        }
        __syncthreads();
        if (tid == 0) { __threadfence(); st_release(&flagG2[g], 1u); }
    }

    float2 ssq = exq;
    if (h == 1) {
        float2 h0q = s_h0q[l];
        ssq.x += h0q.x; ssq.y += h0q.y;
    }

    // ---------------- Phase 3: output ----------------
    sx = ssx; sn = ssn;
    #pragma unroll 8
    for (int t = 0; t < HT; ++t) {
        float2 xv = px[t * 64];
        float2 o;
        float nm, nn, rcpn, mean, d, var, inv, ov;

        nm = (float)((mA >> t) & 1u);
        sx.x += xv.x; sn.x += nm;
        nn = fmaxf(sn.x, 1.f);
        rcpn = frcp(nn);
        mean = sx.x * rcpn;
        d = (xv.x - mean) * nm;
        ssq.x = fmaf(d, d, ssq.x);
        var = ssq.x * rcpn;
        inv = (var > 1e-10f) ? frsq(var) : 1.f;   // std>1e-5 <=> var>1e-10
        ov = (xv.x - mean) * inv;
        o.x = fminf(fmaxf(ov, -100.f), 100.f);

        nm = (float)((mB >> t) & 1u);
        sx.y += xv.y; sn.y += nm;
        nn = fmaxf(sn.y, 1.f);
        rcpn = frcp(nn);
        mean = sx.y * rcpn;
        d = (xv.y - mean) * nm;
        ssq.y = fmaf(d, d, ssq.y);
        var = ssq.y * rcpn;
        inv = (var > 1e-10f) ? frsq(var) : 1.f;
        ov = (xv.y - mean) * inv;
        o.y = fminf(fmaxf(ov, -100.f), 100.f);

        __stcs(&po[t * 64], o);
    }
}

// ---------------- launch ----------------
extern "C" void kernel_launch(void* const* d_in, const int* in_sizes, int n_in,
                              void* d_out, int out_size)
{
    const float* x    = (const float*)d_in[0];
    const float* mask = (const float*)d_in[1];
    float* out        = (float*)d_out;

    revin_init_flags<<<(2 * Bn * NCH + 511) / 512, 512>>>();
    dim3 grid(NCH, Bn);
    revin_kernel<<<grid, 128>>>(x, mask, out);
}